// round 2
// baseline (speedup 1.0000x reference)
#include <cuda_runtime.h>
#include <cuda_bf16.h>
#include <cstdint>
#include <cstddef>

// ---------------------------------------------------------------------------
// Problem constants
// ---------------------------------------------------------------------------
#define BB   32      // batch
#define TT   512     // time
#define EE   512     // embed
#define HH   512     // hidden
#define CC   32      // classes
#define NG   2048    // 4*H gate rows
#define MM   (TT*BB) // 16384 merged (t,b) rows, m = t*32 + b
#define NCTA 128     // scan CTAs (64 per direction)

// ---------------------------------------------------------------------------
// Device scratch (static module memory — no runtime allocation)
// ---------------------------------------------------------------------------
__device__ float    g_e0[MM * EE];               // [m=(t,b)][e]   33.5 MB
__device__ float    g_xw[2][MM][NG];             // [dir][m][4H]   268 MB
__device__ float    g_h1[TT][2*HH][BB];          // [t][feat][b]   67 MB
__device__ float    g_h2[TT][2*HH][BB];          // [t][feat][b]   67 MB
__device__ float    g_hstate[2][2][HH][BB];      // ping-pong [buf][dir][k][b]
__device__ unsigned g_bar_count;
__device__ unsigned g_bar_epoch;

// ---------------------------------------------------------------------------
// Grid barrier: sense-free monotonically-increasing epoch, wrap-safe compare.
// Correctness: __syncthreads gives block-scope release of all threads' STGs to
// tid0; tid0's __threadfence makes them gpu-visible (cumulativity); epoch is
// published with st.release and observed with ld.acquire.
// ---------------------------------------------------------------------------
__device__ __forceinline__ void grid_barrier(unsigned target)
{
    __syncthreads();
    if (threadIdx.x == 0) {
        __threadfence();
        unsigned prev = atomicAdd(&g_bar_count, 1u);
        if (prev == NCTA - 1) {
            g_bar_count = 0;  // ordered before release below
            asm volatile("st.release.gpu.u32 [%0], %1;"
                         :: "l"(&g_bar_epoch), "r"(target) : "memory");
        } else {
            unsigned e;
            do {
                asm volatile("ld.acquire.gpu.u32 %0, [%1];"
                             : "=r"(e) : "l"(&g_bar_epoch) : "memory");
            } while ((int)(e - target) < 0);
        }
    }
    __syncthreads();
}

// ---------------------------------------------------------------------------
// Embedding gather: e0[(t*32+b)][e] = emb[x[b][t]][e].  Coalesced read+write.
// ---------------------------------------------------------------------------
__global__ __launch_bounds__(256) void gather_kernel(const int* __restrict__ x,
                                                     const float* __restrict__ emb)
{
    int warp = (blockIdx.x * 256 + threadIdx.x) >> 5;
    int lane = threadIdx.x & 31;
    int t = warp >> 5, b = warp & 31;
    int tok = x[b * TT + t];
    const float4* src = (const float4*)(emb + (size_t)tok * EE);
    float4*       dst = (float4*)(g_e0 + (size_t)warp * EE);
#pragma unroll
    for (int i = 0; i < 4; i++) dst[lane + 32 * i] = src[lane + 32 * i];
}

// ---------------------------------------------------------------------------
// SGEMM: C[m][n] = sum_k A[m][k] * W[n][k] + (biA[n]+biB[n])
//   AMODE 0: A row-major [M][K]                  (e0)
//   AMODE 1: A is [t][k][b] with m = t*32+b      (h1 written by the scan)
// 128x128x16 tiles, 256 threads, 8x8 per-thread, smem double buffered.
// z-dim selects direction (fwd/bwd weights + output).
// ---------------------------------------------------------------------------
template<int AMODE>
__global__ __launch_bounds__(256) void gemm_kernel(
    const float* __restrict__ A,
    const float* __restrict__ Wf, const float* __restrict__ Wb,
    const float* __restrict__ biAf, const float* __restrict__ biBf,
    const float* __restrict__ biAb, const float* __restrict__ biBb,
    float* __restrict__ Cf, float* __restrict__ Cb,
    int K)
{
    const int N = NG;
    int dir = blockIdx.z;
    const float* W   = dir ? Wb   : Wf;
    const float* biA = dir ? biAb : biAf;
    const float* biB = dir ? biBb : biBf;
    float*       C   = dir ? Cb   : Cf;

    __shared__ float As[2][16][128];
    __shared__ float Bs[2][16][128];

    int tid = threadIdx.x;
    int n0 = blockIdx.x * 128;
    int m0 = blockIdx.y * 128;

    float4 ra[2], rb[2];

    auto loadG = [&](int kt) {
        int k0 = kt * 16;
#pragma unroll
        for (int i = 0; i < 2; i++) {
            int q = i * 256 + tid;
            if (AMODE == 0) {
                int row = q >> 2, kq = q & 3;
                ra[i] = *(const float4*)&A[(size_t)(m0 + row) * K + k0 + kq * 4];
            } else {
                int kk = q >> 5, rest = q & 31, tt = rest >> 3, bq = rest & 7;
                ra[i] = *(const float4*)&A[(size_t)((m0 >> 5) + tt) * ((size_t)K * 32)
                                           + (size_t)(k0 + kk) * 32 + bq * 4];
            }
            int row = q >> 2, kq = q & 3;
            rb[i] = *(const float4*)&W[(size_t)(n0 + row) * K + k0 + kq * 4];
        }
    };
    auto storeS = [&](int buf) {
#pragma unroll
        for (int i = 0; i < 2; i++) {
            int q = i * 256 + tid;
            if (AMODE == 0) {
                int row = q >> 2, kq = q & 3;
                As[buf][kq * 4 + 0][row] = ra[i].x;
                As[buf][kq * 4 + 1][row] = ra[i].y;
                As[buf][kq * 4 + 2][row] = ra[i].z;
                As[buf][kq * 4 + 3][row] = ra[i].w;
            } else {
                int kk = q >> 5, rest = q & 31, tt = rest >> 3, bq = rest & 7;
                *(float4*)&As[buf][kk][tt * 32 + bq * 4] = ra[i];
            }
            int row = q >> 2, kq = q & 3;
            Bs[buf][kq * 4 + 0][row] = rb[i].x;
            Bs[buf][kq * 4 + 1][row] = rb[i].y;
            Bs[buf][kq * 4 + 2][row] = rb[i].z;
            Bs[buf][kq * 4 + 3][row] = rb[i].w;
        }
    };

    float acc[8][8];
#pragma unroll
    for (int i = 0; i < 8; i++)
#pragma unroll
        for (int j = 0; j < 8; j++) acc[i][j] = 0.f;

    int ty = tid >> 4, tx = tid & 15;
    int KT = K / 16;

    loadG(0); storeS(0); __syncthreads();
    for (int kt = 0; kt < KT; kt++) {
        if (kt + 1 < KT) loadG(kt + 1);
        int buf = kt & 1;
#pragma unroll
        for (int kk = 0; kk < 16; kk++) {
            float4 a0 = *(float4*)&As[buf][kk][ty * 8];
            float4 a1 = *(float4*)&As[buf][kk][ty * 8 + 4];
            float4 b0 = *(float4*)&Bs[buf][kk][tx * 8];
            float4 b1 = *(float4*)&Bs[buf][kk][tx * 8 + 4];
            float av[8] = {a0.x, a0.y, a0.z, a0.w, a1.x, a1.y, a1.z, a1.w};
            float bv[8] = {b0.x, b0.y, b0.z, b0.w, b1.x, b1.y, b1.z, b1.w};
#pragma unroll
            for (int i = 0; i < 8; i++)
#pragma unroll
                for (int j = 0; j < 8; j++) acc[i][j] += av[i] * bv[j];
        }
        if (kt + 1 < KT) { storeS((kt + 1) & 1); __syncthreads(); }
    }

    float bs[8];
#pragma unroll
    for (int j = 0; j < 8; j++) {
        int gn = n0 + tx * 8 + j;
        bs[j] = biA[gn] + biB[gn];
    }
#pragma unroll
    for (int i = 0; i < 8; i++) {
        int gm = m0 + ty * 8 + i;
        float4 v0 = make_float4(acc[i][0] + bs[0], acc[i][1] + bs[1],
                                acc[i][2] + bs[2], acc[i][3] + bs[3]);
        float4 v1 = make_float4(acc[i][4] + bs[4], acc[i][5] + bs[5],
                                acc[i][6] + bs[6], acc[i][7] + bs[7]);
        *(float4*)&C[(size_t)gm * N + n0 + tx * 8]     = v0;
        *(float4*)&C[(size_t)gm * N + n0 + tx * 8 + 4] = v1;
    }
}

// ---------------------------------------------------------------------------
// Persistent bidirectional LSTM scan (one layer per launch).
// 128 CTAs: cid&1 = dir, (cid>>1)*8 = first owned hidden unit.
// SMEM: Ws[512 k][32 gate-rows] (64KB, loaded once), hs[512 k][32 b] (64KB,
// restaged per step via __ldcg), part[2][32][32] split-K partials.
// Cell state lives in one register per (unit,batch) thread.
// ---------------------------------------------------------------------------
__device__ __forceinline__ float sigf(float x) { return 1.f / (1.f + expf(-x)); }

__global__ __launch_bounds__(256) void scan_kernel(const float* __restrict__ xw,   // [2][MM][NG]
                                                   const float* __restrict__ WhhF,
                                                   const float* __restrict__ WhhB,
                                                   float* __restrict__ hout)       // [t][2H][b]
{
    extern __shared__ float sm[];
    float* Ws   = sm;            // 16384 floats
    float* hs   = sm + 16384;    // 16384 floats
    float* part = sm + 32768;    // 2048 floats

    int tid = threadIdx.x;
    int cid = blockIdx.x;
    int dir = cid & 1;
    int u0  = (cid >> 1) * 8;
    const float* Whh = dir ? WhhB : WhhF;
    const float* xwD = xw + (size_t)dir * MM * NG;

    __shared__ unsigned sbase;
    if (tid == 0) sbase = *(volatile unsigned*)&g_bar_epoch;

    // Load this CTA's Whh slice, stored k-major: Ws[k][r], r = gate*8+uu.
#pragma unroll
    for (int i = 0; i < 16; i++) {
        int q  = i * 256 + tid;        // float4 index, 32 rows x 128 f4
        int r  = q >> 7;
        int kq = q & 127;
        int gate = r >> 3, uu = r & 7;
        float4 w = *(const float4*)&Whh[(size_t)(gate * HH + u0 + uu) * HH + kq * 4];
        Ws[(kq * 4 + 0) * 32 + r] = w.x;
        Ws[(kq * 4 + 1) * 32 + r] = w.y;
        Ws[(kq * 4 + 2) * 32 + r] = w.z;
        Ws[(kq * 4 + 3) * 32 + r] = w.w;
    }
    // Zero this CTA's slice of hstate buf 0.
    {
        int uu = tid >> 5, b = tid & 31;
        g_hstate[0][dir][u0 + uu][b] = 0.f;
    }
    __syncthreads();
    unsigned base = sbase;
    grid_barrier(base + 1);

    // GEMM-phase mapping (split-K over 2 groups of 128 threads, 2x4 tiles)
    int kg = tid >> 7, t2 = tid & 127;
    int rr = t2 >> 3, cc = t2 & 7;     // rows {2rr,2rr+1}, cols {4cc..4cc+3}
    // c-phase mapping
    int uuC = tid >> 5, bC = tid & 31;
    float creg = 0.f;

    for (int s = 0; s < TT; ++s) {
        int t = dir ? (TT - 1 - s) : s;

        // Stage h (L2-coherent: ldcg — L1 is stale across the ping-pong).
        const float4* hsrc = (const float4*)&g_hstate[s & 1][dir][0][0];
#pragma unroll
        for (int i = 0; i < 16; i++) {
            int q = i * 256 + tid;
            *(((float4*)hs) + q) = __ldcg(hsrc + q);
        }
        // Prefetch this thread's xw gate inputs (overlaps the GEMM below).
        float xwv[4];
        const float* xp = &xwD[(size_t)(t * 32 + bC) * NG + u0 + uuC];
#pragma unroll
        for (int g = 0; g < 4; g++) xwv[g] = __ldg(&xp[g * HH]);
        __syncthreads();

        // 32x32x512 micro-GEMM, split-K
        float a00 = 0.f, a01 = 0.f, a02 = 0.f, a03 = 0.f;
        float a10 = 0.f, a11 = 0.f, a12 = 0.f, a13 = 0.f;
        {
            int kbeg = kg * 256, kend = kbeg + 256;
#pragma unroll 4
            for (int k = kbeg; k < kend; k++) {
                float2 w = *(float2*)&Ws[k * 32 + 2 * rr];
                float4 h = *(float4*)&hs[k * 32 + 4 * cc];
                a00 += w.x * h.x; a01 += w.x * h.y; a02 += w.x * h.z; a03 += w.x * h.w;
                a10 += w.y * h.x; a11 += w.y * h.y; a12 += w.y * h.z; a13 += w.y * h.w;
            }
        }
        {
            float* p = &part[kg * 1024 + (2 * rr) * 32 + 4 * cc];
            p[0] = a00; p[1] = a01; p[2] = a02; p[3] = a03;
            p[32] = a10; p[33] = a11; p[34] = a12; p[35] = a13;
        }
        __syncthreads();

        // Gate combine + cell update (thread = (unit uuC, batch bC))
        int r0 = uuC * 32 + bC;
        float gi = part[(0 * 8) * 32 + r0] + part[1024 + (0 * 8) * 32 + r0] + xwv[0];
        float gf = part[(1 * 8) * 32 + r0] + part[1024 + (1 * 8) * 32 + r0] + xwv[1];
        float gg = part[(2 * 8) * 32 + r0] + part[1024 + (2 * 8) * 32 + r0] + xwv[2];
        float go = part[(3 * 8) * 32 + r0] + part[1024 + (3 * 8) * 32 + r0] + xwv[3];

        creg = sigf(gf) * creg + sigf(gi) * tanhf(gg);
        float hv = sigf(go) * tanhf(creg);

        g_hstate[(s + 1) & 1][dir][u0 + uuC][bC] = hv;
        hout[(size_t)t * (2 * HH * BB) + (size_t)(dir * HH + u0 + uuC) * BB + bC] = hv;

        grid_barrier(base + 2 + s);
    }
}

// ---------------------------------------------------------------------------
// Classifier + log_softmax + transpose.  One CTA per t; Wc SMEM-resident.
// thread = (b = tid/8, 4 classes c = (tid%8)*4 .. +3); 8-lane shuffle LSE.
// ---------------------------------------------------------------------------
__global__ __launch_bounds__(256) void classifier_kernel(
    const float* __restrict__ truth, const int* __restrict__ tf_p,
    const float* __restrict__ Wc, const float* __restrict__ bc,
    float* __restrict__ out)
{
    extern __shared__ float Wcs[];        // 32*1025 floats
    __shared__ float bcs[CC];
    int tid = threadIdx.x, t = blockIdx.x;

    for (int i = tid; i < CC * (2 * HH + 1); i += 256) Wcs[i] = Wc[i];
    if (tid < CC) bcs[tid] = bc[tid];
    __syncthreads();

    int b = tid >> 3, cg = tid & 7, c0 = cg * 4;
    int tf = *tf_p;
    float past = (tf && t > 0) ? truth[b * TT + (t - 1)] : 0.f;

    float acc[4];
#pragma unroll
    for (int j = 0; j < 4; j++)
        acc[j] = bcs[c0 + j] + Wcs[(c0 + j) * 1025] * past;

    const float* h2 = &g_h2[0][0][0] + (size_t)t * (2 * HH * BB) + b;
#pragma unroll 4
    for (int f = 0; f < 2 * HH; f++) {
        float hv = __ldg(&h2[(size_t)f * BB]);
#pragma unroll
        for (int j = 0; j < 4; j++)
            acc[j] += Wcs[(c0 + j) * 1025 + 1 + f] * hv;
    }

    float m = fmaxf(fmaxf(acc[0], acc[1]), fmaxf(acc[2], acc[3]));
#pragma unroll
    for (int off = 1; off < 8; off <<= 1)
        m = fmaxf(m, __shfl_xor_sync(0xffffffffu, m, off));
    float ssum = 0.f;
#pragma unroll
    for (int j = 0; j < 4; j++) ssum += expf(acc[j] - m);
#pragma unroll
    for (int off = 1; off < 8; off <<= 1)
        ssum += __shfl_xor_sync(0xffffffffu, ssum, off);
    float lse = m + logf(ssum);

#pragma unroll
    for (int j = 0; j < 4; j++)
        out[(size_t)b * (CC * TT) + (size_t)(c0 + j) * TT + t] = acc[j] - lse;
}

// ---------------------------------------------------------------------------
// Host launcher
// ---------------------------------------------------------------------------
extern "C" void kernel_launch(void* const* d_in, const int* in_sizes, int n_in,
                              void* d_out, int out_size)
{
    const int*   x      = (const int*)  d_in[0];
    const float* truth  = (const float*)d_in[1];
    const int*   tf     = (const int*)  d_in[2];
    const float* emb    = (const float*)d_in[3];
    const float* Wih0f  = (const float*)d_in[4];
    const float* Whh0f  = (const float*)d_in[5];
    const float* bih0f  = (const float*)d_in[6];
    const float* bhh0f  = (const float*)d_in[7];
    const float* Wih0b  = (const float*)d_in[8];
    const float* Whh0b  = (const float*)d_in[9];
    const float* bih0b  = (const float*)d_in[10];
    const float* bhh0b  = (const float*)d_in[11];
    const float* Wih1f  = (const float*)d_in[12];
    const float* Whh1f  = (const float*)d_in[13];
    const float* bih1f  = (const float*)d_in[14];
    const float* bhh1f  = (const float*)d_in[15];
    const float* Wih1b  = (const float*)d_in[16];
    const float* Whh1b  = (const float*)d_in[17];
    const float* bih1b  = (const float*)d_in[18];
    const float* bhh1b  = (const float*)d_in[19];
    const float* Wc     = (const float*)d_in[20];
    const float* bc     = (const float*)d_in[21];

    void *pe0, *pxw, *ph1, *ph2;
    cudaGetSymbolAddress(&pe0, g_e0);
    cudaGetSymbolAddress(&pxw, g_xw);
    cudaGetSymbolAddress(&ph1, g_h1);
    cudaGetSymbolAddress(&ph2, g_h2);
    float* e0  = (float*)pe0;
    float* xw  = (float*)pxw;
    float* xw0 = xw;
    float* xw1 = xw + (size_t)MM * NG;
    float* h1  = (float*)ph1;
    float* h2  = (float*)ph2;

    const int SCAN_SMEM = (16384 + 16384 + 2048) * 4;   // 139264 B
    const int CLS_SMEM  = CC * (2 * HH + 1) * 4;        // 131200 B
    cudaFuncSetAttribute(scan_kernel,
                         cudaFuncAttributeMaxDynamicSharedMemorySize, SCAN_SMEM);
    cudaFuncSetAttribute(classifier_kernel,
                         cudaFuncAttributeMaxDynamicSharedMemorySize, CLS_SMEM);

    // 1) embedding gather
    gather_kernel<<<2048, 256>>>(x, emb);

    // 2) layer-0 input GEMM (both directions via z)
    gemm_kernel<0><<<dim3(NG / 128, MM / 128, 2), 256>>>(
        e0, Wih0f, Wih0b, bih0f, bhh0f, bih0b, bhh0b, xw0, xw1, EE);

    // 3) layer-0 scan
    scan_kernel<<<NCTA, 256, SCAN_SMEM>>>(xw, Whh0f, Whh0b, h1);

    // 4) layer-1 input GEMM (A = h1 in [t][k][b] layout)
    gemm_kernel<1><<<dim3(NG / 128, MM / 128, 2), 256>>>(
        h1, Wih1f, Wih1b, bih1f, bhh1f, bih1b, bhh1b, xw0, xw1, 2 * HH);

    // 5) layer-1 scan
    scan_kernel<<<NCTA, 256, SCAN_SMEM>>>(xw, Whh1f, Whh1b, h2);

    // 6) classifier + log_softmax + transpose
    classifier_kernel<<<TT, 256, CLS_SMEM>>>(truth, tf, Wc, bc, (float*)d_out);
}

// round 4
// speedup vs baseline: 1.2560x; 1.2560x over previous
#include <cuda_runtime.h>
#include <cuda_bf16.h>
#include <cstdint>
#include <cstddef>

// ---------------------------------------------------------------------------
// Problem constants
// ---------------------------------------------------------------------------
#define BB   32      // batch
#define TT   512     // time
#define EE   512     // embed
#define HH   512     // hidden
#define CC   32      // classes
#define NG   2048    // 4*H gate rows
#define MM   (TT*BB) // 16384 merged (t,b) rows, m = t*32 + b
#define NCTA 128     // scan CTAs (64 per direction)

// ---------------------------------------------------------------------------
// Device scratch (static module memory — no runtime allocation)
// ---------------------------------------------------------------------------
__device__ float    g_e0[MM * EE];               // [m][e] row-major
__device__ float    g_xw[2][MM][NG];             // [dir][m][4H]
__device__ float    g_h1[MM * 2 * HH];           // [m][feat] row-major
__device__ float    g_h2[MM * 2 * HH];           // [m][feat] row-major
__device__ float    g_hstate[2][2][HH][BB];      // ping-pong [buf][dir][k][b]
__device__ unsigned g_bar_count;
__device__ unsigned g_bar_epoch;

// ---------------------------------------------------------------------------
// Small PTX helpers (sm_80-baseline only — no tcgen05 on this compile target)
// ---------------------------------------------------------------------------
__device__ __forceinline__ uint32_t smem_u32(const void* p) {
    return (uint32_t)__cvta_generic_to_shared(p);
}
__device__ __forceinline__ void cpa16(uint32_t dst, const void* src) {
    asm volatile("cp.async.cg.shared.global [%0], [%1], 16;\n" :: "r"(dst), "l"(src));
}
#define CP_COMMIT() asm volatile("cp.async.commit_group;\n" ::: "memory")
#define CP_WAIT(n)  asm volatile("cp.async.wait_group %0;\n" :: "n"(n) : "memory")

__device__ __forceinline__ uint32_t f2tf32(float x) {
    uint32_t r;
    asm("cvt.rna.tf32.f32 %0, %1;\n" : "=r"(r) : "f"(x));
    return r;
}
__device__ __forceinline__ void mma_tf32(float* d, const uint32_t* a, const uint32_t* b) {
    asm volatile(
        "mma.sync.aligned.m16n8k8.row.col.f32.tf32.tf32.f32 "
        "{%0, %1, %2, %3}, {%4, %5, %6, %7}, {%8, %9}, {%0, %1, %2, %3};\n"
        : "+f"(d[0]), "+f"(d[1]), "+f"(d[2]), "+f"(d[3])
        : "r"(a[0]), "r"(a[1]), "r"(a[2]), "r"(a[3]), "r"(b[0]), "r"(b[1]));
}

// ---------------------------------------------------------------------------
// Grid barrier (validated in R1).
// ---------------------------------------------------------------------------
__device__ __forceinline__ void grid_barrier(unsigned target)
{
    __syncthreads();
    if (threadIdx.x == 0) {
        __threadfence();
        unsigned prev = atomicAdd(&g_bar_count, 1u);
        if (prev == NCTA - 1) {
            g_bar_count = 0;
            asm volatile("st.release.gpu.u32 [%0], %1;"
                         :: "l"(&g_bar_epoch), "r"(target) : "memory");
        } else {
            unsigned e;
            do {
                asm volatile("ld.acquire.gpu.u32 %0, [%1];"
                             : "=r"(e) : "l"(&g_bar_epoch) : "memory");
            } while ((int)(e - target) < 0);
        }
    }
    __syncthreads();
}

// ---------------------------------------------------------------------------
// Embedding gather: e0[(t*32+b)][e] = emb[x[b][t]][e].
// ---------------------------------------------------------------------------
__global__ __launch_bounds__(256) void gather_kernel(const int* __restrict__ x,
                                                     const float* __restrict__ emb)
{
    int warp = (blockIdx.x * 256 + threadIdx.x) >> 5;
    int lane = threadIdx.x & 31;
    int t = warp >> 5, b = warp & 31;
    int tok = x[b * TT + t];
    const float4* src = (const float4*)(emb + (size_t)tok * EE);
    float4*       dst = (float4*)(g_e0 + (size_t)warp * EE);
#pragma unroll
    for (int i = 0; i < 4; i++) dst[lane + 32 * i] = src[lane + 32 * i];
}

// ---------------------------------------------------------------------------
// tf32 mma.sync GEMM: C[m][n] = sum_k A[m][k]*W[n][k] + (biA[n]+biB[n]).
// 128x128 block tile, 8 warps (2x4), warp tile 64x32, K-tile 32,
// double-buffered cp.async, pitch-36 SMEM (bank-conflict-free frag loads).
// Grid (NG/128, MM/128, 2 dir), 256 threads.
// ---------------------------------------------------------------------------
#define GPITCH 36
static constexpr int GEMM_SMEM = 2 * 2 * 128 * GPITCH * 4;   // 73728 B

template<int K>
__global__ __launch_bounds__(256) void tc_gemm_kernel(
    const float* __restrict__ A,
    const float* __restrict__ Wf, const float* __restrict__ Wb,
    const float* __restrict__ biAf, const float* __restrict__ biBf,
    const float* __restrict__ biAb, const float* __restrict__ biBb,
    float* __restrict__ Cf, float* __restrict__ Cb)
{
    constexpr int KT = K / 32;
    extern __shared__ float sg[];
    // layout: As[2][128][36], Bs[2][128][36]
    float* As[2] = { sg,                sg + 128 * GPITCH };
    float* Bs[2] = { sg + 2 * 128 * GPITCH, sg + 3 * 128 * GPITCH };
    __shared__ float bias[128];

    int tid  = threadIdx.x;
    int lane = tid & 31;
    int warp = tid >> 5;
    int wm   = warp & 1;          // 2 warps in M (64 rows each)
    int wn   = warp >> 1;         // 4 warps in N (32 cols each)

    int dir = blockIdx.z;
    const float* W   = dir ? Wb   : Wf;
    const float* biA = dir ? biAb : biAf;
    const float* biB = dir ? biBb : biBf;
    float*       C   = dir ? Cb   : Cf;
    int n0 = blockIdx.x * 128;
    int m0 = blockIdx.y * 128;

    if (tid < 128) bias[tid] = biA[n0 + tid] + biB[n0 + tid];

    uint32_t sA[2] = { smem_u32(As[0]), smem_u32(As[1]) };
    uint32_t sB[2] = { smem_u32(Bs[0]), smem_u32(Bs[1]) };

    auto load_tile = [&](int kt, int s) {
        const float* Ab = A + (size_t)m0 * K + kt * 32;
        const float* Wp = W + (size_t)n0 * K + kt * 32;
#pragma unroll
        for (int i = 0; i < 4; i++) {
            int q = i * 256 + tid, row = q >> 3, f4 = q & 7;
            cpa16(sA[s] + row * (GPITCH * 4) + f4 * 16, Ab + (size_t)row * K + f4 * 4);
        }
#pragma unroll
        for (int i = 0; i < 4; i++) {
            int q = i * 256 + tid, row = q >> 3, f4 = q & 7;
            cpa16(sB[s] + row * (GPITCH * 4) + f4 * 16, Wp + (size_t)row * K + f4 * 4);
        }
        CP_COMMIT();
    };

    float acc[4][4][4];
#pragma unroll
    for (int i = 0; i < 4; i++)
#pragma unroll
        for (int j = 0; j < 4; j++)
#pragma unroll
            for (int q = 0; q < 4; q++) acc[i][j][q] = 0.f;

    load_tile(0, 0);
    if (KT > 1) load_tile(1, 1);

    int r4 = lane >> 2, c4 = lane & 3;

    for (int kt = 0; kt < KT; kt++) {
        if (kt + 1 < KT) { CP_WAIT(1); } else { CP_WAIT(0); }
        __syncthreads();
        int s = kt & 1;
        const float* Ab = As[s];
        const float* Bb = Bs[s];
#pragma unroll
        for (int ks = 0; ks < 4; ks++) {
            int kc = ks * 8 + c4;
            uint32_t af[4][4], bf[4][2];
#pragma unroll
            for (int mt = 0; mt < 4; mt++) {
                int row = wm * 64 + mt * 16 + r4;
                af[mt][0] = f2tf32(Ab[row * GPITCH + kc]);
                af[mt][1] = f2tf32(Ab[(row + 8) * GPITCH + kc]);
                af[mt][2] = f2tf32(Ab[row * GPITCH + kc + 4]);
                af[mt][3] = f2tf32(Ab[(row + 8) * GPITCH + kc + 4]);
            }
#pragma unroll
            for (int nt = 0; nt < 4; nt++) {
                int col = wn * 32 + nt * 8 + r4;
                bf[nt][0] = f2tf32(Bb[col * GPITCH + kc]);
                bf[nt][1] = f2tf32(Bb[col * GPITCH + kc + 4]);
            }
#pragma unroll
            for (int mt = 0; mt < 4; mt++)
#pragma unroll
                for (int nt = 0; nt < 4; nt++)
                    mma_tf32(acc[mt][nt], af[mt], bf[nt]);
        }
        __syncthreads();
        if (kt + 2 < KT) load_tile(kt + 2, s);
    }

    // Epilogue: c0,c1 at (row, 2c4), (row, 2c4+1); c2,c3 at row+8.
#pragma unroll
    for (int mt = 0; mt < 4; mt++) {
        int row = m0 + wm * 64 + mt * 16 + r4;
#pragma unroll
        for (int nt = 0; nt < 4; nt++) {
            int colL = wn * 32 + nt * 8 + 2 * c4;      // block-local col
            int col  = n0 + colL;
            float2 v0 = make_float2(acc[mt][nt][0] + bias[colL],
                                    acc[mt][nt][1] + bias[colL + 1]);
            float2 v1 = make_float2(acc[mt][nt][2] + bias[colL],
                                    acc[mt][nt][3] + bias[colL + 1]);
            *(float2*)&C[(size_t)row * NG + col]       = v0;
            *(float2*)&C[(size_t)(row + 8) * NG + col] = v1;
        }
    }
}

// ---------------------------------------------------------------------------
// Persistent bidirectional LSTM scan (hout row-major [m=(t,b)][feat]).
// ---------------------------------------------------------------------------
__device__ __forceinline__ float sigf(float x) { return 1.f / (1.f + expf(-x)); }

__global__ __launch_bounds__(256) void scan_kernel(const float* __restrict__ xw,   // [2][MM][NG]
                                                   const float* __restrict__ WhhF,
                                                   const float* __restrict__ WhhB,
                                                   float* __restrict__ hout)       // [m][2H]
{
    extern __shared__ float sm[];
    float* Ws   = sm;            // 16384 floats
    float* hs   = sm + 16384;    // 16384 floats
    float* part = sm + 32768;    // 2048 floats
    float* hb   = sm + 34816;    // 256 floats (h staging tile [b][u])

    int tid = threadIdx.x;
    int cid = blockIdx.x;
    int dir = cid & 1;
    int u0  = (cid >> 1) * 8;
    const float* Whh = dir ? WhhB : WhhF;
    const float* xwD = xw + (size_t)dir * MM * NG;

    __shared__ unsigned sbase;
    if (tid == 0) sbase = *(volatile unsigned*)&g_bar_epoch;

#pragma unroll
    for (int i = 0; i < 16; i++) {
        int q  = i * 256 + tid;
        int r  = q >> 7;
        int kq = q & 127;
        int gate = r >> 3, uu = r & 7;
        float4 w = *(const float4*)&Whh[(size_t)(gate * HH + u0 + uu) * HH + kq * 4];
        Ws[(kq * 4 + 0) * 32 + r] = w.x;
        Ws[(kq * 4 + 1) * 32 + r] = w.y;
        Ws[(kq * 4 + 2) * 32 + r] = w.z;
        Ws[(kq * 4 + 3) * 32 + r] = w.w;
    }
    {
        int uu = tid >> 5, b = tid & 31;
        g_hstate[0][dir][u0 + uu][b] = 0.f;
    }
    __syncthreads();
    unsigned base = sbase;
    grid_barrier(base + 1);

    int kg = tid >> 7, t2 = tid & 127;
    int rr = t2 >> 3, cc = t2 & 7;
    int uuC = tid >> 5, bC = tid & 31;
    float creg = 0.f;

    for (int s = 0; s < TT; ++s) {
        int t = dir ? (TT - 1 - s) : s;

        const float4* hsrc = (const float4*)&g_hstate[s & 1][dir][0][0];
#pragma unroll
        for (int i = 0; i < 16; i++) {
            int q = i * 256 + tid;
            *(((float4*)hs) + q) = __ldcg(hsrc + q);
        }
        float xwv[4];
        const float* xp = &xwD[(size_t)(t * 32 + bC) * NG + u0 + uuC];
#pragma unroll
        for (int g = 0; g < 4; g++) xwv[g] = __ldg(&xp[g * HH]);
        __syncthreads();

        float a00 = 0.f, a01 = 0.f, a02 = 0.f, a03 = 0.f;
        float a10 = 0.f, a11 = 0.f, a12 = 0.f, a13 = 0.f;
        {
            int kbeg = kg * 256, kend = kbeg + 256;
#pragma unroll 4
            for (int k = kbeg; k < kend; k++) {
                float2 w = *(float2*)&Ws[k * 32 + 2 * rr];
                float4 h = *(float4*)&hs[k * 32 + 4 * cc];
                a00 += w.x * h.x; a01 += w.x * h.y; a02 += w.x * h.z; a03 += w.x * h.w;
                a10 += w.y * h.x; a11 += w.y * h.y; a12 += w.y * h.z; a13 += w.y * h.w;
            }
        }
        {
            float* p = &part[kg * 1024 + (2 * rr) * 32 + 4 * cc];
            p[0] = a00; p[1] = a01; p[2] = a02; p[3] = a03;
            p[32] = a10; p[33] = a11; p[34] = a12; p[35] = a13;
        }
        __syncthreads();

        int r0 = uuC * 32 + bC;
        float gi = part[(0 * 8) * 32 + r0] + part[1024 + (0 * 8) * 32 + r0] + xwv[0];
        float gf = part[(1 * 8) * 32 + r0] + part[1024 + (1 * 8) * 32 + r0] + xwv[1];
        float gg = part[(2 * 8) * 32 + r0] + part[1024 + (2 * 8) * 32 + r0] + xwv[2];
        float go = part[(3 * 8) * 32 + r0] + part[1024 + (3 * 8) * 32 + r0] + xwv[3];

        creg = sigf(gf) * creg + sigf(gi) * tanhf(gg);
        float hv = sigf(go) * tanhf(creg);

        g_hstate[(s + 1) & 1][dir][u0 + uuC][bC] = hv;
        hb[bC * 8 + uuC] = hv;
        __syncthreads();
        if (tid < 64) {                 // coalesced row-major hout write
            int b = tid >> 1, half = tid & 1;
            float4 v = *(float4*)&hb[b * 8 + half * 4];
            *(float4*)&hout[((size_t)t * 32 + b) * (2 * HH) + dir * HH + u0 + half * 4] = v;
        }

        grid_barrier(base + 2 + s);
    }
}

// ---------------------------------------------------------------------------
// Classifier + log_softmax + transpose (h2 row-major [m][feat]).
// ---------------------------------------------------------------------------
__global__ __launch_bounds__(256) void classifier_kernel(
    const float* __restrict__ truth, const int* __restrict__ tf_p,
    const float* __restrict__ Wc, const float* __restrict__ bc,
    float* __restrict__ out)
{
    extern __shared__ float Wcs[];        // 32*1025 floats
    __shared__ float bcs[CC];
    int tid = threadIdx.x, t = blockIdx.x;

    for (int i = tid; i < CC * (2 * HH + 1); i += 256) Wcs[i] = Wc[i];
    if (tid < CC) bcs[tid] = bc[tid];
    __syncthreads();

    int b = tid >> 3, cg = tid & 7, c0 = cg * 4;
    int tf = *tf_p;
    float past = (tf && t > 0) ? truth[b * TT + (t - 1)] : 0.f;

    float acc[4];
#pragma unroll
    for (int j = 0; j < 4; j++)
        acc[j] = bcs[c0 + j] + Wcs[(c0 + j) * 1025] * past;

    const float4* hp = (const float4*)&g_h2[((size_t)t * 32 + b) * (2 * HH)];
#pragma unroll 2
    for (int fi = 0; fi < 256; fi++) {
        float4 h = __ldg(hp + fi);
        int f = fi * 4;
#pragma unroll
        for (int j = 0; j < 4; j++) {
            const float* wr = &Wcs[(c0 + j) * 1025 + 1 + f];
            acc[j] += wr[0] * h.x + wr[1] * h.y + wr[2] * h.z + wr[3] * h.w;
        }
    }

    float m = fmaxf(fmaxf(acc[0], acc[1]), fmaxf(acc[2], acc[3]));
#pragma unroll
    for (int off = 1; off < 8; off <<= 1)
        m = fmaxf(m, __shfl_xor_sync(0xffffffffu, m, off));
    float ssum = 0.f;
#pragma unroll
    for (int j = 0; j < 4; j++) ssum += expf(acc[j] - m);
#pragma unroll
    for (int off = 1; off < 8; off <<= 1)
        ssum += __shfl_xor_sync(0xffffffffu, ssum, off);
    float lse = m + logf(ssum);

#pragma unroll
    for (int j = 0; j < 4; j++)
        out[(size_t)b * (CC * TT) + (size_t)(c0 + j) * TT + t] = acc[j] - lse;
}

// ---------------------------------------------------------------------------
// Host launcher
// ---------------------------------------------------------------------------
extern "C" void kernel_launch(void* const* d_in, const int* in_sizes, int n_in,
                              void* d_out, int out_size)
{
    const int*   x      = (const int*)  d_in[0];
    const float* truth  = (const float*)d_in[1];
    const int*   tf     = (const int*)  d_in[2];
    const float* emb    = (const float*)d_in[3];
    const float* Wih0f  = (const float*)d_in[4];
    const float* Whh0f  = (const float*)d_in[5];
    const float* bih0f  = (const float*)d_in[6];
    const float* bhh0f  = (const float*)d_in[7];
    const float* Wih0b  = (const float*)d_in[8];
    const float* Whh0b  = (const float*)d_in[9];
    const float* bih0b  = (const float*)d_in[10];
    const float* bhh0b  = (const float*)d_in[11];
    const float* Wih1f  = (const float*)d_in[12];
    const float* Whh1f  = (const float*)d_in[13];
    const float* bih1f  = (const float*)d_in[14];
    const float* bhh1f  = (const float*)d_in[15];
    const float* Wih1b  = (const float*)d_in[16];
    const float* Whh1b  = (const float*)d_in[17];
    const float* bih1b  = (const float*)d_in[18];
    const float* bhh1b  = (const float*)d_in[19];
    const float* Wc     = (const float*)d_in[20];
    const float* bc     = (const float*)d_in[21];

    void *pe0, *pxw, *ph1, *ph2;
    cudaGetSymbolAddress(&pe0, g_e0);
    cudaGetSymbolAddress(&pxw, g_xw);
    cudaGetSymbolAddress(&ph1, g_h1);
    cudaGetSymbolAddress(&ph2, g_h2);
    float* e0  = (float*)pe0;
    float* xw  = (float*)pxw;
    float* xw0 = xw;
    float* xw1 = xw + (size_t)MM * NG;
    float* h1  = (float*)ph1;
    float* h2  = (float*)ph2;

    const int SCAN_SMEM = (16384 + 16384 + 2048 + 256) * 4;   // 140288 B
    const int CLS_SMEM  = CC * (2 * HH + 1) * 4;              // 131200 B
    cudaFuncSetAttribute(scan_kernel,
                         cudaFuncAttributeMaxDynamicSharedMemorySize, SCAN_SMEM);
    cudaFuncSetAttribute(classifier_kernel,
                         cudaFuncAttributeMaxDynamicSharedMemorySize, CLS_SMEM);
    cudaFuncSetAttribute(tc_gemm_kernel<512>,
                         cudaFuncAttributeMaxDynamicSharedMemorySize, GEMM_SMEM);
    cudaFuncSetAttribute(tc_gemm_kernel<1024>,
                         cudaFuncAttributeMaxDynamicSharedMemorySize, GEMM_SMEM);

    // 1) embedding gather
    gather_kernel<<<2048, 256>>>(x, emb);

    // 2) layer-0 input GEMM (tf32 mma.sync, both directions via z)
    tc_gemm_kernel<512><<<dim3(NG / 128, MM / 128, 2), 256, GEMM_SMEM>>>(
        e0, Wih0f, Wih0b, bih0f, bhh0f, bih0b, bhh0b, xw0, xw1);

    // 3) layer-0 scan
    scan_kernel<<<NCTA, 256, SCAN_SMEM>>>(xw, Whh0f, Whh0b, h1);

    // 4) layer-1 input GEMM (A = h1, row-major [m][1024])
    tc_gemm_kernel<1024><<<dim3(NG / 128, MM / 128, 2), 256, GEMM_SMEM>>>(
        h1, Wih1f, Wih1b, bih1f, bhh1f, bih1b, bhh1b, xw0, xw1);

    // 5) layer-1 scan
    scan_kernel<<<NCTA, 256, SCAN_SMEM>>>(xw, Whh1f, Whh1b, h2);

    // 6) classifier + log_softmax + transpose
    classifier_kernel<<<TT, 256, CLS_SMEM>>>(truth, tf, Wc, bc, (float*)d_out);
}

// round 5
// speedup vs baseline: 1.7404x; 1.3856x over previous
#include <cuda_runtime.h>
#include <cuda_bf16.h>
#include <cstdint>
#include <cstddef>

// ---------------------------------------------------------------------------
// Problem constants
// ---------------------------------------------------------------------------
#define BB   32      // batch
#define TT   512     // time
#define EE   512     // embed
#define HH   512     // hidden
#define CC   32      // classes
#define NG   2048    // 4*H gate rows
#define MM   (TT*BB) // 16384 merged (t,b) rows, m = t*32 + b
#define NCTA 128     // scan CTAs (64 per direction)

// ---------------------------------------------------------------------------
// Device scratch (static module memory — no runtime allocation)
// ---------------------------------------------------------------------------
__device__ __nv_bfloat16 g_e0b[MM * EE];           // [m][e] bf16
__device__ __nv_bfloat16 g_h1b[MM * 2 * HH];       // [m][feat] bf16 (GEMM input)
__device__ __nv_bfloat16 g_w0f[NG * EE];           // bf16 weight copies
__device__ __nv_bfloat16 g_w0b[NG * EE];
__device__ __nv_bfloat16 g_w1f[NG * 2 * HH];
__device__ __nv_bfloat16 g_w1b[NG * 2 * HH];
__device__ float    g_xw[2][MM][NG];               // [dir][m][4H] fp32
__device__ float    g_h2[MM * 2 * HH];             // [m][feat] fp32 (classifier)
__device__ float    g_hstate[2][2][HH][BB];        // ping-pong [buf][dir][k][b]
__device__ unsigned g_bar_count;
__device__ unsigned g_bar_epoch;

// ---------------------------------------------------------------------------
// PTX helpers (sm_80-baseline only — no tcgen05 on this compile target)
// ---------------------------------------------------------------------------
__device__ __forceinline__ uint32_t smem_u32(const void* p) {
    return (uint32_t)__cvta_generic_to_shared(p);
}
__device__ __forceinline__ void cpa16(uint32_t dst, const void* src) {
    asm volatile("cp.async.cg.shared.global [%0], [%1], 16;\n" :: "r"(dst), "l"(src));
}
#define CP_COMMIT() asm volatile("cp.async.commit_group;\n" ::: "memory")
#define CP_WAIT(n)  asm volatile("cp.async.wait_group %0;\n" :: "n"(n) : "memory")

__device__ __forceinline__ void ldsm4(uint32_t* r, uint32_t addr) {
    asm volatile("ldmatrix.sync.aligned.m8n8.x4.shared.b16 {%0, %1, %2, %3}, [%4];\n"
                 : "=r"(r[0]), "=r"(r[1]), "=r"(r[2]), "=r"(r[3]) : "r"(addr));
}
__device__ __forceinline__ void mma_bf16(float* d, const uint32_t* a, const uint32_t* b) {
    asm volatile(
        "mma.sync.aligned.m16n8k16.row.col.f32.bf16.bf16.f32 "
        "{%0, %1, %2, %3}, {%4, %5, %6, %7}, {%8, %9}, {%0, %1, %2, %3};\n"
        : "+f"(d[0]), "+f"(d[1]), "+f"(d[2]), "+f"(d[3])
        : "r"(a[0]), "r"(a[1]), "r"(a[2]), "r"(a[3]), "r"(b[0]), "r"(b[1]));
}
__device__ __forceinline__ uint2 f4_to_bf16x4(float4 v) {
    __nv_bfloat162 lo = __floats2bfloat162_rn(v.x, v.y);
    __nv_bfloat162 hi = __floats2bfloat162_rn(v.z, v.w);
    uint2 r;
    r.x = *(uint32_t*)&lo;
    r.y = *(uint32_t*)&hi;
    return r;
}

// ---------------------------------------------------------------------------
// Grid barrier (validated R1/R2/R4).
// ---------------------------------------------------------------------------
__device__ __forceinline__ void grid_barrier(unsigned target)
{
    __syncthreads();
    if (threadIdx.x == 0) {
        __threadfence();
        unsigned prev = atomicAdd(&g_bar_count, 1u);
        if (prev == NCTA - 1) {
            g_bar_count = 0;
            asm volatile("st.release.gpu.u32 [%0], %1;"
                         :: "l"(&g_bar_epoch), "r"(target) : "memory");
        } else {
            unsigned e;
            do {
                asm volatile("ld.acquire.gpu.u32 %0, [%1];"
                             : "=r"(e) : "l"(&g_bar_epoch) : "memory");
            } while ((int)(e - target) < 0);
        }
    }
    __syncthreads();
}

// ---------------------------------------------------------------------------
// fp32 -> bf16 weight conversion (tiny pre-pass; 4 launches)
// ---------------------------------------------------------------------------
__global__ __launch_bounds__(256) void cvt_kernel(const float* __restrict__ src,
                                                  __nv_bfloat16* __restrict__ dst,
                                                  int n4)
{
    int i = blockIdx.x * 256 + threadIdx.x;
    if (i < n4) {
        float4 v = *(const float4*)&src[i * 4];
        *(uint2*)&dst[i * 4] = f4_to_bf16x4(v);
    }
}

// ---------------------------------------------------------------------------
// Embedding gather (writes bf16): e0b[(t*32+b)][e] = bf16(emb[x[b][t]][e]).
// ---------------------------------------------------------------------------
__global__ __launch_bounds__(256) void gather_kernel(const int* __restrict__ x,
                                                     const float* __restrict__ emb)
{
    int warp = (blockIdx.x * 256 + threadIdx.x) >> 5;
    int lane = threadIdx.x & 31;
    int t = warp >> 5, b = warp & 31;
    int tok = x[b * TT + t];
    const float4* src = (const float4*)(emb + (size_t)tok * EE);
    __nv_bfloat16* dst = g_e0b + (size_t)warp * EE;
#pragma unroll
    for (int i = 0; i < 4; i++) {
        float4 v = src[lane + 32 * i];
        *(uint2*)&dst[(lane + 32 * i) * 4] = f4_to_bf16x4(v);
    }
}

// ---------------------------------------------------------------------------
// bf16 mma.sync GEMM: C[m][n] = sum_k A[m][k]*W[n][k] + (biA[n]+biB[n]).
// 128x128 block tile, 8 warps (2x4), warp tile 64x32, K-tile 32 (2 k16 steps),
// double-buffered cp.async, ldmatrix fragments, pitch-80B SMEM rows
// ((5r+c) mod 8 quad-bank spread -> conflict-free LDSM).
// Grid (NG/128, MM/128, 2 dir), 256 threads.
// ---------------------------------------------------------------------------
static constexpr int GSTAGE = 128 * 80;                 // bytes per matrix stage
static constexpr int GEMMB_SMEM = 4 * GSTAGE;           // 40960 B

template<int K>
__global__ __launch_bounds__(256) void bf16_gemm_kernel(
    const __nv_bfloat16* __restrict__ A,
    const __nv_bfloat16* __restrict__ Wf, const __nv_bfloat16* __restrict__ Wb,
    const float* __restrict__ biAf, const float* __restrict__ biBf,
    const float* __restrict__ biAb, const float* __restrict__ biBb,
    float* __restrict__ Cf, float* __restrict__ Cb)
{
    constexpr int KT = K / 32;
    extern __shared__ char sg[];
    __shared__ float bias[128];

    int tid  = threadIdx.x;
    int lane = tid & 31;
    int warp = tid >> 5;
    int wm   = warp & 1;          // 2 warps in M (64 rows each)
    int wn   = warp >> 1;         // 4 warps in N (32 cols each)

    int dir = blockIdx.z;
    const __nv_bfloat16* W = dir ? Wb : Wf;
    const float* biA = dir ? biAb : biAf;
    const float* biB = dir ? biBb : biBf;
    float*       C   = dir ? Cb   : Cf;
    int n0 = blockIdx.x * 128;
    int m0 = blockIdx.y * 128;

    if (tid < 128) bias[tid] = biA[n0 + tid] + biB[n0 + tid];

    uint32_t sA[2] = { smem_u32(sg),              smem_u32(sg + GSTAGE) };
    uint32_t sB[2] = { smem_u32(sg + 2 * GSTAGE), smem_u32(sg + 3 * GSTAGE) };

    auto load_tile = [&](int kt, int s) {
        const __nv_bfloat16* Ab = A + (size_t)m0 * K + kt * 32;
        const __nv_bfloat16* Wp = W + (size_t)n0 * K + kt * 32;
#pragma unroll
        for (int i = 0; i < 2; i++) {
            int q = i * 256 + tid, row = q >> 2, ch = q & 3;
            cpa16(sA[s] + row * 80 + ch * 16, Ab + (size_t)row * K + ch * 8);
            cpa16(sB[s] + row * 80 + ch * 16, Wp + (size_t)row * K + ch * 8);
        }
        CP_COMMIT();
    };

    float acc[4][4][4];
#pragma unroll
    for (int i = 0; i < 4; i++)
#pragma unroll
        for (int j = 0; j < 4; j++)
#pragma unroll
            for (int q = 0; q < 4; q++) acc[i][j][q] = 0.f;

    load_tile(0, 0);
    if (KT > 1) load_tile(1, 1);

    int mat  = lane >> 3;
    int lrow = lane & 7;
    int rofs = (mat & 1) * 8 + lrow;     // row offset within 16-row tile
    int cofs = mat >> 1;                 // k-chunk offset within k16 step

    for (int kt = 0; kt < KT; kt++) {
        if (kt + 1 < KT) { CP_WAIT(1); } else { CP_WAIT(0); }
        __syncthreads();
        int s = kt & 1;
#pragma unroll
        for (int ks = 0; ks < 2; ks++) {
            uint32_t af[4][4], bfr[4][2];
            int ch = ks * 2 + cofs;
#pragma unroll
            for (int mt = 0; mt < 4; mt++) {
                int row = wm * 64 + mt * 16 + rofs;
                ldsm4(af[mt], sA[s] + row * 80 + ch * 16);
            }
#pragma unroll
            for (int np = 0; np < 2; np++) {
                int row = wn * 32 + np * 16 + rofs;
                uint32_t r4[4];
                ldsm4(r4, sB[s] + row * 80 + ch * 16);
                bfr[np * 2 + 0][0] = r4[0]; bfr[np * 2 + 0][1] = r4[2];
                bfr[np * 2 + 1][0] = r4[1]; bfr[np * 2 + 1][1] = r4[3];
            }
#pragma unroll
            for (int mt = 0; mt < 4; mt++)
#pragma unroll
                for (int nt = 0; nt < 4; nt++)
                    mma_bf16(acc[mt][nt], af[mt], bfr[nt]);
        }
        __syncthreads();
        if (kt + 2 < KT) load_tile(kt + 2, s);
    }

    int r4l = lane >> 2, c4 = lane & 3;
#pragma unroll
    for (int mt = 0; mt < 4; mt++) {
        int row = m0 + wm * 64 + mt * 16 + r4l;
#pragma unroll
        for (int nt = 0; nt < 4; nt++) {
            int colL = wn * 32 + nt * 8 + 2 * c4;
            int col  = n0 + colL;
            float2 v0 = make_float2(acc[mt][nt][0] + bias[colL],
                                    acc[mt][nt][1] + bias[colL + 1]);
            float2 v1 = make_float2(acc[mt][nt][2] + bias[colL],
                                    acc[mt][nt][3] + bias[colL + 1]);
            *(float2*)&C[(size_t)row * NG + col]       = v0;
            *(float2*)&C[(size_t)(row + 8) * NG + col] = v1;
        }
    }
}

// ---------------------------------------------------------------------------
// Persistent bidirectional LSTM scan. 4-way split-K, 4x4 register tiles
// (32B LDS feeds 16 FMA). Recurrence pure fp32. BF16OUT selects hout format:
// bf16 [m][2H] (layer-0 -> GEMM input) or fp32 [m][2H] (layer-1 -> classifier).
// ---------------------------------------------------------------------------
__device__ __forceinline__ float sigf(float x) { return 1.f / (1.f + expf(-x)); }

template<int BF16OUT>
__global__ __launch_bounds__(256) void scan_kernel(const float* __restrict__ xw,   // [2][MM][NG]
                                                   const float* __restrict__ WhhF,
                                                   const float* __restrict__ WhhB,
                                                   void* __restrict__ hout)
{
    extern __shared__ float sm[];
    float* Ws   = sm;            // 16384 floats  [k][r=gate*8+uu]
    float* hs   = sm + 16384;    // 16384 floats  [k][b]
    float* part = sm + 32768;    // 4096 floats   [4][32 r][32 b]
    float* hb   = sm + 36864;    // 256 floats    [b][u]

    int tid = threadIdx.x;
    int cid = blockIdx.x;
    int dir = cid & 1;
    int u0  = (cid >> 1) * 8;
    const float* Whh = dir ? WhhB : WhhF;
    const float* xwD = xw + (size_t)dir * MM * NG;

    __shared__ unsigned sbase;
    if (tid == 0) sbase = *(volatile unsigned*)&g_bar_epoch;

#pragma unroll
    for (int i = 0; i < 16; i++) {
        int q  = i * 256 + tid;
        int r  = q >> 7;
        int kq = q & 127;
        int gate = r >> 3, uu = r & 7;
        float4 w = *(const float4*)&Whh[(size_t)(gate * HH + u0 + uu) * HH + kq * 4];
        Ws[(kq * 4 + 0) * 32 + r] = w.x;
        Ws[(kq * 4 + 1) * 32 + r] = w.y;
        Ws[(kq * 4 + 2) * 32 + r] = w.z;
        Ws[(kq * 4 + 3) * 32 + r] = w.w;
    }
    {
        int uu = tid >> 5, b = tid & 31;
        g_hstate[0][dir][u0 + uu][b] = 0.f;
    }
    __syncthreads();
    unsigned base = sbase;
    grid_barrier(base + 1);

    // GEMM phase: kg = K-slice group (4 x 128 k), 64 threads per group,
    // thread tile = rows 4rr..+3 (gate rows), cols 4cc..+3 (batch).
    int kg = tid >> 6, t2 = tid & 63;
    int rr = t2 >> 3, cc = t2 & 7;
    // combine phase mapping
    int uuC = tid >> 5, bC = tid & 31;
    float creg = 0.f;

    for (int s = 0; s < TT; ++s) {
        int t = dir ? (TT - 1 - s) : s;

        const float4* hsrc = (const float4*)&g_hstate[s & 1][dir][0][0];
#pragma unroll
        for (int i = 0; i < 16; i++) {
            int q = i * 256 + tid;
            *(((float4*)hs) + q) = __ldcg(hsrc + q);
        }
        float xwv[4];
        const float* xp = &xwD[(size_t)(t * 32 + bC) * NG + u0 + uuC];
#pragma unroll
        for (int g = 0; g < 4; g++) xwv[g] = __ldg(&xp[g * HH]);
        __syncthreads();

        float a[4][4];
#pragma unroll
        for (int i = 0; i < 4; i++)
#pragma unroll
            for (int j = 0; j < 4; j++) a[i][j] = 0.f;
        {
            int kbeg = kg * 128, kend = kbeg + 128;
#pragma unroll 4
            for (int k = kbeg; k < kend; k++) {
                float4 w = *(float4*)&Ws[k * 32 + 4 * rr];
                float4 h = *(float4*)&hs[k * 32 + 4 * cc];
                a[0][0] += w.x * h.x; a[0][1] += w.x * h.y; a[0][2] += w.x * h.z; a[0][3] += w.x * h.w;
                a[1][0] += w.y * h.x; a[1][1] += w.y * h.y; a[1][2] += w.y * h.z; a[1][3] += w.y * h.w;
                a[2][0] += w.z * h.x; a[2][1] += w.z * h.y; a[2][2] += w.z * h.z; a[2][3] += w.z * h.w;
                a[3][0] += w.w * h.x; a[3][1] += w.w * h.y; a[3][2] += w.w * h.z; a[3][3] += w.w * h.w;
            }
        }
        {
            float* p = &part[kg * 1024 + (4 * rr) * 32 + 4 * cc];
#pragma unroll
            for (int i = 0; i < 4; i++)
                *(float4*)&p[i * 32] = make_float4(a[i][0], a[i][1], a[i][2], a[i][3]);
        }
        __syncthreads();

        // Gate combine + cell update (thread = (unit uuC, batch bC))
        float gv[4];
#pragma unroll
        for (int g = 0; g < 4; g++) {
            int idx = (g * 8 + uuC) * 32 + bC;
            gv[g] = part[idx] + part[1024 + idx] + part[2048 + idx] + part[3072 + idx]
                  + xwv[g];
        }
        creg = sigf(gv[1]) * creg + sigf(gv[0]) * tanhf(gv[2]);
        float hv = sigf(gv[3]) * tanhf(creg);

        g_hstate[(s + 1) & 1][dir][u0 + uuC][bC] = hv;
        hb[bC * 8 + uuC] = hv;
        __syncthreads();
        if (tid < 64) {                 // coalesced row-major hout write
            int b = tid >> 1, half = tid & 1;
            float4 v = *(float4*)&hb[b * 8 + half * 4];
            size_t off = ((size_t)t * 32 + b) * (2 * HH) + dir * HH + u0 + half * 4;
            if (BF16OUT)
                *(uint2*)&((__nv_bfloat16*)hout)[off] = f4_to_bf16x4(v);
            else
                *(float4*)&((float*)hout)[off] = v;
        }

        grid_barrier(base + 2 + s);
    }
}

// ---------------------------------------------------------------------------
// Classifier + log_softmax + transpose (h2 row-major fp32 [m][feat]).
// ---------------------------------------------------------------------------
__global__ __launch_bounds__(256) void classifier_kernel(
    const float* __restrict__ truth, const int* __restrict__ tf_p,
    const float* __restrict__ Wc, const float* __restrict__ bc,
    float* __restrict__ out)
{
    extern __shared__ float Wcs[];        // 32*1025 floats
    __shared__ float bcs[CC];
    int tid = threadIdx.x, t = blockIdx.x;

    for (int i = tid; i < CC * (2 * HH + 1); i += 256) Wcs[i] = Wc[i];
    if (tid < CC) bcs[tid] = bc[tid];
    __syncthreads();

    int b = tid >> 3, cg = tid & 7, c0 = cg * 4;
    int tf = *tf_p;
    float past = (tf && t > 0) ? truth[b * TT + (t - 1)] : 0.f;

    float acc[4];
#pragma unroll
    for (int j = 0; j < 4; j++)
        acc[j] = bcs[c0 + j] + Wcs[(c0 + j) * 1025] * past;

    const float4* hp = (const float4*)&g_h2[((size_t)t * 32 + b) * (2 * HH)];
#pragma unroll 2
    for (int fi = 0; fi < 256; fi++) {
        float4 h = __ldg(hp + fi);
        int f = fi * 4;
#pragma unroll
        for (int j = 0; j < 4; j++) {
            const float* wr = &Wcs[(c0 + j) * 1025 + 1 + f];
            acc[j] += wr[0] * h.x + wr[1] * h.y + wr[2] * h.z + wr[3] * h.w;
        }
    }

    float m = fmaxf(fmaxf(acc[0], acc[1]), fmaxf(acc[2], acc[3]));
#pragma unroll
    for (int off = 1; off < 8; off <<= 1)
        m = fmaxf(m, __shfl_xor_sync(0xffffffffu, m, off));
    float ssum = 0.f;
#pragma unroll
    for (int j = 0; j < 4; j++) ssum += expf(acc[j] - m);
#pragma unroll
    for (int off = 1; off < 8; off <<= 1)
        ssum += __shfl_xor_sync(0xffffffffu, ssum, off);
    float lse = m + logf(ssum);

#pragma unroll
    for (int j = 0; j < 4; j++)
        out[(size_t)b * (CC * TT) + (size_t)(c0 + j) * TT + t] = acc[j] - lse;
}

// ---------------------------------------------------------------------------
// Host launcher
// ---------------------------------------------------------------------------
extern "C" void kernel_launch(void* const* d_in, const int* in_sizes, int n_in,
                              void* d_out, int out_size)
{
    const int*   x      = (const int*)  d_in[0];
    const float* truth  = (const float*)d_in[1];
    const int*   tf     = (const int*)  d_in[2];
    const float* emb    = (const float*)d_in[3];
    const float* Wih0f  = (const float*)d_in[4];
    const float* Whh0f  = (const float*)d_in[5];
    const float* bih0f  = (const float*)d_in[6];
    const float* bhh0f  = (const float*)d_in[7];
    const float* Wih0b  = (const float*)d_in[8];
    const float* Whh0b  = (const float*)d_in[9];
    const float* bih0b  = (const float*)d_in[10];
    const float* bhh0b  = (const float*)d_in[11];
    const float* Wih1f  = (const float*)d_in[12];
    const float* Whh1f  = (const float*)d_in[13];
    const float* bih1f  = (const float*)d_in[14];
    const float* bhh1f  = (const float*)d_in[15];
    const float* Wih1b  = (const float*)d_in[16];
    const float* Whh1b  = (const float*)d_in[17];
    const float* bih1b  = (const float*)d_in[18];
    const float* bhh1b  = (const float*)d_in[19];
    const float* Wc     = (const float*)d_in[20];
    const float* bc     = (const float*)d_in[21];

    void *pe0b, *pxw, *ph1b, *ph2, *pw0f, *pw0b, *pw1f, *pw1b;
    cudaGetSymbolAddress(&pe0b, g_e0b);
    cudaGetSymbolAddress(&pxw,  g_xw);
    cudaGetSymbolAddress(&ph1b, g_h1b);
    cudaGetSymbolAddress(&ph2,  g_h2);
    cudaGetSymbolAddress(&pw0f, g_w0f);
    cudaGetSymbolAddress(&pw0b, g_w0b);
    cudaGetSymbolAddress(&pw1f, g_w1f);
    cudaGetSymbolAddress(&pw1b, g_w1b);
    __nv_bfloat16* e0b = (__nv_bfloat16*)pe0b;
    __nv_bfloat16* h1b = (__nv_bfloat16*)ph1b;
    __nv_bfloat16* w0f = (__nv_bfloat16*)pw0f;
    __nv_bfloat16* w0b = (__nv_bfloat16*)pw0b;
    __nv_bfloat16* w1f = (__nv_bfloat16*)pw1f;
    __nv_bfloat16* w1b = (__nv_bfloat16*)pw1b;
    float* xw  = (float*)pxw;
    float* xw0 = xw;
    float* xw1 = xw + (size_t)MM * NG;
    float* h2  = (float*)ph2;

    const int SCAN_SMEM = (16384 + 16384 + 4096 + 256) * 4;   // 148480 B
    const int CLS_SMEM  = CC * (2 * HH + 1) * 4;              // 131200 B
    cudaFuncSetAttribute(scan_kernel<1>,
                         cudaFuncAttributeMaxDynamicSharedMemorySize, SCAN_SMEM);
    cudaFuncSetAttribute(scan_kernel<0>,
                         cudaFuncAttributeMaxDynamicSharedMemorySize, SCAN_SMEM);
    cudaFuncSetAttribute(classifier_kernel,
                         cudaFuncAttributeMaxDynamicSharedMemorySize, CLS_SMEM);
    cudaFuncSetAttribute(bf16_gemm_kernel<512>,
                         cudaFuncAttributeMaxDynamicSharedMemorySize, GEMMB_SMEM);
    cudaFuncSetAttribute(bf16_gemm_kernel<1024>,
                         cudaFuncAttributeMaxDynamicSharedMemorySize, GEMMB_SMEM);

    // 0) weight conversion pre-pass (bf16 copies)
    cvt_kernel<<<(NG * EE / 4 + 255) / 256, 256>>>(Wih0f, w0f, NG * EE / 4);
    cvt_kernel<<<(NG * EE / 4 + 255) / 256, 256>>>(Wih0b, w0b, NG * EE / 4);
    cvt_kernel<<<(NG * 2 * HH / 4 + 255) / 256, 256>>>(Wih1f, w1f, NG * 2 * HH / 4);
    cvt_kernel<<<(NG * 2 * HH / 4 + 255) / 256, 256>>>(Wih1b, w1b, NG * 2 * HH / 4);

    // 1) embedding gather (bf16)
    gather_kernel<<<2048, 256>>>(x, emb);

    // 2) layer-0 input GEMM (bf16 mma.sync + ldmatrix, both directions via z)
    bf16_gemm_kernel<512><<<dim3(NG / 128, MM / 128, 2), 256, GEMMB_SMEM>>>(
        e0b, w0f, w0b, bih0f, bhh0f, bih0b, bhh0b, xw0, xw1);

    // 3) layer-0 scan (emits bf16 h1 for the next GEMM)
    scan_kernel<1><<<NCTA, 256, SCAN_SMEM>>>(xw, Whh0f, Whh0b, h1b);

    // 4) layer-1 input GEMM (A = h1 bf16, row-major [m][1024])
    bf16_gemm_kernel<1024><<<dim3(NG / 128, MM / 128, 2), 256, GEMMB_SMEM>>>(
        h1b, w1f, w1b, bih1f, bhh1f, bih1b, bhh1b, xw0, xw1);

    // 5) layer-1 scan (emits fp32 h2 for the classifier)
    scan_kernel<0><<<NCTA, 256, SCAN_SMEM>>>(xw, Whh1f, Whh1b, h2);

    // 6) classifier + log_softmax + transpose
    classifier_kernel<<<TT, 256, CLS_SMEM>>>(truth, tf, Wc, bc, (float*)d_out);
}